// round 1
// baseline (speedup 1.0000x reference)
#include <cuda_runtime.h>
#include <math.h>

#define N_NODES 50000
#define N_EDGES 600000
#define IN_DIM  128
#define HID_DIM 512
#define OUT_DIM 2

// ---------------- scratch (static device globals; no allocs allowed) --------
__device__ float g_agg1[N_NODES * IN_DIM];    // 25.6 MB
__device__ float g_deg [N_NODES];             // in-degree -> inverted in place
__device__ float g_h   [N_NODES * HID_DIM];   // 102.4 MB
__device__ float g_agg2[N_NODES * HID_DIM];   // 102.4 MB

// ---------------- zero scratch ----------------------------------------------
__global__ void zero_kernel() {
    long long total = (long long)N_NODES * IN_DIM + (long long)N_NODES * HID_DIM + N_NODES;
    for (long long i = (long long)blockIdx.x * blockDim.x + threadIdx.x;
         i < total; i += (long long)gridDim.x * blockDim.x) {
        if (i < (long long)N_NODES * IN_DIM)       g_agg1[i] = 0.f;
        else if (i < (long long)N_NODES * IN_DIM + (long long)N_NODES * HID_DIM)
            g_agg2[i - (long long)N_NODES * IN_DIM] = 0.f;
        else
            g_deg[i - (long long)N_NODES * IN_DIM - (long long)N_NODES * HID_DIM] = 0.f;
    }
}

// ---------------- scatter layer-1: agg1[dst] += x[src] (d=128) --------------
// one warp per edge; each lane handles 4 floats
__global__ void scatter1_kernel(const float* __restrict__ x,
                                const int* __restrict__ edge_index) {
    long long tid = (long long)blockIdx.x * blockDim.x + threadIdx.x;
    long long e = tid >> 5;
    int lane = (int)(tid & 31);
    if (e >= N_EDGES) return;
    int src = edge_index[e];
    int dst = edge_index[N_EDGES + e];
    const float4 v = *reinterpret_cast<const float4*>(x + (long long)src * IN_DIM + lane * 4);
    float* base = g_agg1 + (long long)dst * IN_DIM + lane * 4;
    atomicAdd(base + 0, v.x);
    atomicAdd(base + 1, v.y);
    atomicAdd(base + 2, v.z);
    atomicAdd(base + 3, v.w);
    if (lane == 0) atomicAdd(&g_deg[dst], 1.0f);
}

// ---------------- invert degrees --------------------------------------------
__global__ void finalize_deg_kernel() {
    int i = blockIdx.x * blockDim.x + threadIdx.x;
    if (i < N_NODES) g_deg[i] = 1.0f / fmaxf(g_deg[i], 1.0f);
}

// ---------------- SGEMM layer-1 ----------------------------------------------
// h = relu( (agg1 * inv_deg) @ W1l + b1 + x @ W1r )
// virtual A: [M=N_NODES, K=256], k<128 -> agg1*inv_deg, k>=128 -> x
// virtual B: [K=256, N=512],     k<128 -> W1l,          k>=128 -> W1r
// tiles: BM=64, BN=64, BK=32; 256 threads; each thread 4x4 micro-tile
__global__ __launch_bounds__(256)
void gemm1_kernel(const float* __restrict__ x,
                  const float* __restrict__ W1l,
                  const float* __restrict__ b1,
                  const float* __restrict__ W1r) {
    constexpr int BM = 64, BN = 64, BK = 32;
    __shared__ float As[BK][BM + 1];
    __shared__ float Bs[BK][BN];

    const int block_m = blockIdx.y * BM;
    const int block_n = blockIdx.x * BN;
    const int tid = threadIdx.x;
    const int tx = tid % 16;      // -> 4 output cols
    const int ty = tid / 16;      // -> 4 output rows

    float acc[4][4] = {};

    // loader mapping
    const int a_row  = tid >> 2;          // 0..63
    const int a_kcol = (tid & 3) * 8;     // 0,8,16,24
    const int b_krow = tid >> 3;          // 0..31
    const int b_ncol = (tid & 7) * 8;     // 0..56

    for (int k0 = 0; k0 < 2 * IN_DIM; k0 += BK) {
        // ---- load A tile (transposed into As[k][m]) ----
        {
            int m = block_m + a_row;
            float vals[8];
            if (m < N_NODES) {
                if (k0 < IN_DIM) {
                    const float invd = g_deg[m];
                    const float4 v0 = *reinterpret_cast<const float4*>(
                        g_agg1 + (long long)m * IN_DIM + k0 + a_kcol);
                    const float4 v1 = *reinterpret_cast<const float4*>(
                        g_agg1 + (long long)m * IN_DIM + k0 + a_kcol + 4);
                    vals[0]=v0.x*invd; vals[1]=v0.y*invd; vals[2]=v0.z*invd; vals[3]=v0.w*invd;
                    vals[4]=v1.x*invd; vals[5]=v1.y*invd; vals[6]=v1.z*invd; vals[7]=v1.w*invd;
                } else {
                    const float4 v0 = *reinterpret_cast<const float4*>(
                        x + (long long)m * IN_DIM + (k0 - IN_DIM) + a_kcol);
                    const float4 v1 = *reinterpret_cast<const float4*>(
                        x + (long long)m * IN_DIM + (k0 - IN_DIM) + a_kcol + 4);
                    vals[0]=v0.x; vals[1]=v0.y; vals[2]=v0.z; vals[3]=v0.w;
                    vals[4]=v1.x; vals[5]=v1.y; vals[6]=v1.z; vals[7]=v1.w;
                }
            } else {
                #pragma unroll
                for (int i = 0; i < 8; i++) vals[i] = 0.f;
            }
            #pragma unroll
            for (int i = 0; i < 8; i++) As[a_kcol + i][a_row] = vals[i];
        }
        // ---- load B tile ----
        {
            int k = k0 + b_krow;
            const float* W = (k < IN_DIM) ? W1l : W1r;
            int krel = (k < IN_DIM) ? k : (k - IN_DIM);
            const float4 v0 = *reinterpret_cast<const float4*>(
                W + (long long)krel * HID_DIM + block_n + b_ncol);
            const float4 v1 = *reinterpret_cast<const float4*>(
                W + (long long)krel * HID_DIM + block_n + b_ncol + 4);
            Bs[b_krow][b_ncol + 0] = v0.x; Bs[b_krow][b_ncol + 1] = v0.y;
            Bs[b_krow][b_ncol + 2] = v0.z; Bs[b_krow][b_ncol + 3] = v0.w;
            Bs[b_krow][b_ncol + 4] = v1.x; Bs[b_krow][b_ncol + 5] = v1.y;
            Bs[b_krow][b_ncol + 6] = v1.z; Bs[b_krow][b_ncol + 7] = v1.w;
        }
        __syncthreads();

        #pragma unroll
        for (int kk = 0; kk < BK; kk++) {
            float a[4], b[4];
            #pragma unroll
            for (int i = 0; i < 4; i++) a[i] = As[kk][ty * 4 + i];
            #pragma unroll
            for (int j = 0; j < 4; j++) b[j] = Bs[kk][tx * 4 + j];
            #pragma unroll
            for (int i = 0; i < 4; i++)
                #pragma unroll
                for (int j = 0; j < 4; j++)
                    acc[i][j] += a[i] * b[j];
        }
        __syncthreads();
    }

    // ---- epilogue: + b1, relu, store to g_h ----
    #pragma unroll
    for (int i = 0; i < 4; i++) {
        int m = block_m + ty * 4 + i;
        if (m >= N_NODES) continue;
        #pragma unroll
        for (int j = 0; j < 4; j++) {
            int n = block_n + tx * 4 + j;
            float v = acc[i][j] + b1[n];
            g_h[(long long)m * HID_DIM + n] = fmaxf(v, 0.f);
        }
    }
}

// ---------------- scatter layer-2: agg2[dst] += h[src] (d=512) --------------
// 128 threads per edge, 4 floats each
__global__ void scatter2_kernel(const int* __restrict__ edge_index) {
    long long tid = (long long)blockIdx.x * blockDim.x + threadIdx.x;
    long long e = tid >> 7;
    int lane = (int)(tid & 127);
    if (e >= N_EDGES) return;
    int src = edge_index[e];
    int dst = edge_index[N_EDGES + e];
    const float4 v = *reinterpret_cast<const float4*>(
        g_h + (long long)src * HID_DIM + lane * 4);
    float* base = g_agg2 + (long long)dst * HID_DIM + lane * 4;
    atomicAdd(base + 0, v.x);
    atomicAdd(base + 1, v.y);
    atomicAdd(base + 2, v.z);
    atomicAdd(base + 3, v.w);
}

// ---------------- layer-2 (d=2) + log_softmax: warp per node ----------------
__global__ void gemm2_kernel(const float* __restrict__ W2l,
                             const float* __restrict__ b2,
                             const float* __restrict__ W2r,
                             float* __restrict__ out) {
    int warp = (blockIdx.x * blockDim.x + threadIdx.x) >> 5;
    int lane = threadIdx.x & 31;
    if (warp >= N_NODES) return;
    const int n = warp;
    const float invd = g_deg[n];

    float acc0 = 0.f, acc1 = 0.f;
    const float* aggr = g_agg2 + (long long)n * HID_DIM;
    const float* hrow = g_h   + (long long)n * HID_DIM;
    #pragma unroll
    for (int k = lane; k < HID_DIM; k += 32) {
        float a  = aggr[k] * invd;
        float hv = hrow[k];
        float wl0 = __ldg(W2l + k * 2 + 0), wl1 = __ldg(W2l + k * 2 + 1);
        float wr0 = __ldg(W2r + k * 2 + 0), wr1 = __ldg(W2r + k * 2 + 1);
        acc0 += a * wl0 + hv * wr0;
        acc1 += a * wl1 + hv * wr1;
    }
    #pragma unroll
    for (int off = 16; off > 0; off >>= 1) {
        acc0 += __shfl_down_sync(0xffffffff, acc0, off);
        acc1 += __shfl_down_sync(0xffffffff, acc1, off);
    }
    if (lane == 0) {
        float o0 = acc0 + b2[0];
        float o1 = acc1 + b2[1];
        float m = fmaxf(o0, o1);
        float lse = m + logf(expf(o0 - m) + expf(o1 - m));
        out[n * 2 + 0] = o0 - lse;
        out[n * 2 + 1] = o1 - lse;
    }
}

// ---------------- launcher ----------------------------------------------------
extern "C" void kernel_launch(void* const* d_in, const int* in_sizes, int n_in,
                              void* d_out, int out_size) {
    const float* x    = (const float*)d_in[0];
    const float* W1l  = (const float*)d_in[1];
    const float* b1   = (const float*)d_in[2];
    const float* W1r  = (const float*)d_in[3];
    const float* W2l  = (const float*)d_in[4];
    const float* b2   = (const float*)d_in[5];
    const float* W2r  = (const float*)d_in[6];
    const int*   ei   = (const int*)d_in[7];
    float* out = (float*)d_out;

    // 1. zero scratch
    zero_kernel<<<2048, 256>>>();

    // 2. scatter layer 1 (warp per edge)
    {
        long long threads = (long long)N_EDGES * 32;
        int blocks = (int)((threads + 255) / 256);
        scatter1_kernel<<<blocks, 256>>>(x, ei);
    }

    // 3. invert degrees
    finalize_deg_kernel<<<(N_NODES + 255) / 256, 256>>>();

    // 4. layer-1 GEMM fused (mean, +b1, relu)
    {
        dim3 grid(HID_DIM / 64, (N_NODES + 63) / 64);
        gemm1_kernel<<<grid, 256>>>(x, W1l, b1, W1r);
    }

    // 5. scatter layer 2 (128 threads per edge)
    {
        long long threads = (long long)N_EDGES * 128;
        int blocks = (int)((threads + 255) / 256);
        scatter2_kernel<<<blocks, 256>>>(ei);
    }

    // 6. layer-2 + log_softmax (warp per node)
    {
        int warps = N_NODES;
        int blocks = (warps * 32 + 255) / 256;
        gemm2_kernel<<<blocks, 256>>>(W2l, b2, W2r, out);
    }
}

// round 2
// speedup vs baseline: 2.5418x; 2.5418x over previous
#include <cuda_runtime.h>
#include <math.h>

#define N_NODES 50000
#define N_EDGES 600000
#define IN_DIM  128
#define HID_DIM 512
#define OUT_DIM 2

// ---------------- scratch ----------------------------------------------------
__device__ float g_agg1[N_NODES * IN_DIM];  // 25.6 MB: sum of x over in-edges
__device__ float g_deg [N_NODES];           // in-degree -> inverted in place
__device__ float g_pq  [N_NODES * 4];       // per node: pl0,pl1 (h@W2l), pr0,pr1 (h@W2r)
__device__ float g_q   [N_NODES * 2];       // scattered pl sums

// ---------------- zero scratch ----------------------------------------------
__global__ void zero_kernel() {
    const long long n_agg = (long long)N_NODES * IN_DIM;
    const long long total = n_agg + N_NODES + N_NODES * 4 + N_NODES * 2;
    for (long long i = (long long)blockIdx.x * blockDim.x + threadIdx.x;
         i < total; i += (long long)gridDim.x * blockDim.x) {
        if (i < n_agg) g_agg1[i] = 0.f;
        else {
            long long r = i - n_agg;
            if (r < N_NODES) g_deg[r] = 0.f;
            else if (r < N_NODES + (long long)N_NODES * 4) g_pq[r - N_NODES] = 0.f;
            else g_q[r - N_NODES - (long long)N_NODES * 4] = 0.f;
        }
    }
}

// ---------------- scatter layer-1: agg1[dst] += x[src] (d=128) --------------
__global__ void scatter1_kernel(const float* __restrict__ x,
                                const int* __restrict__ edge_index) {
    long long tid = (long long)blockIdx.x * blockDim.x + threadIdx.x;
    long long e = tid >> 5;
    int lane = (int)(tid & 31);
    if (e >= N_EDGES) return;
    int src = edge_index[e];
    int dst = edge_index[N_EDGES + e];
    const float4 v = *reinterpret_cast<const float4*>(x + (long long)src * IN_DIM + lane * 4);
    float* base = g_agg1 + (long long)dst * IN_DIM + lane * 4;
    atomicAdd(base + 0, v.x);
    atomicAdd(base + 1, v.y);
    atomicAdd(base + 2, v.z);
    atomicAdd(base + 3, v.w);
    if (lane == 0) atomicAdd(&g_deg[dst], 1.0f);
}

// ---------------- invert degrees --------------------------------------------
__global__ void finalize_deg_kernel() {
    int i = blockIdx.x * blockDim.x + threadIdx.x;
    if (i < N_NODES) g_deg[i] = 1.0f / fmaxf(g_deg[i], 1.0f);
}

// ---------------- layer-1 SGEMM fused with layer-2 projection ----------------
// h_row = relu( (agg1*invd) @ W1l + b1 + x @ W1r )     [never stored]
// g_pq[m] += [ h_tile @ W2l_tile , h_tile @ W2r_tile ]  (atomic across 4 n-blocks)
// virtual A: [M, K=256]  k<128 -> agg1*invd, else x
// virtual B: [K=256, N=512]  k<128 -> W1l, else W1r
// tiles BM=128, BN=128, BK=8; 256 threads; 8x8 micro-tile
__global__ __launch_bounds__(256, 2)
void gemm1_kernel(const float* __restrict__ x,
                  const float* __restrict__ W1l,
                  const float* __restrict__ b1,
                  const float* __restrict__ W1r,
                  const float* __restrict__ W2l,
                  const float* __restrict__ W2r) {
    constexpr int BM = 128, BN = 128, BK = 8;
    __shared__ float As[BK][BM];
    __shared__ float Bs[BK][BN];
    __shared__ float Wc[BN][4];   // W2l / W2r columns for this n-block

    const int block_m = blockIdx.y * BM;
    const int block_n = blockIdx.x * BN;
    const int tid = threadIdx.x;
    const int tx = tid & 15;   // 16 col-groups of 8
    const int ty = tid >> 4;   // 16 row-groups of 8

    // A loader: each thread one float4 of one row
    const int a_row = tid & 127;          // 0..127
    const int a_k4  = (tid >> 7) * 4;     // 0 or 4
    // B loader
    const int b_row  = tid >> 5;          // 0..7
    const int b_col4 = (tid & 31) * 4;    // 0..124

    const int a_m = block_m + a_row;
    const bool a_ok = (a_m < N_NODES);
    const float invd = a_ok ? g_deg[a_m] : 0.f;

    float acc[8][8] = {};

    for (int k0 = 0; k0 < 2 * IN_DIM; k0 += BK) {
        // ---- load A tile transposed ----
        {
            float4 v = make_float4(0.f, 0.f, 0.f, 0.f);
            if (a_ok) {
                if (k0 < IN_DIM) {
                    v = *reinterpret_cast<const float4*>(
                        g_agg1 + (long long)a_m * IN_DIM + k0 + a_k4);
                    v.x *= invd; v.y *= invd; v.z *= invd; v.w *= invd;
                } else {
                    v = *reinterpret_cast<const float4*>(
                        x + (long long)a_m * IN_DIM + (k0 - IN_DIM) + a_k4);
                }
            }
            As[a_k4 + 0][a_row] = v.x;
            As[a_k4 + 1][a_row] = v.y;
            As[a_k4 + 2][a_row] = v.z;
            As[a_k4 + 3][a_row] = v.w;
        }
        // ---- load B tile ----
        {
            int k = k0 + b_row;
            const float* W = (k < IN_DIM) ? W1l : W1r;
            int krel = (k < IN_DIM) ? k : (k - IN_DIM);
            const float4 v = *reinterpret_cast<const float4*>(
                W + (long long)krel * HID_DIM + block_n + b_col4);
            *reinterpret_cast<float4*>(&Bs[b_row][b_col4]) = v;
        }
        __syncthreads();

        #pragma unroll
        for (int kk = 0; kk < BK; kk++) {
            float a[8], b[8];
            *reinterpret_cast<float4*>(&a[0]) = *reinterpret_cast<const float4*>(&As[kk][ty * 8]);
            *reinterpret_cast<float4*>(&a[4]) = *reinterpret_cast<const float4*>(&As[kk][ty * 8 + 4]);
            *reinterpret_cast<float4*>(&b[0]) = *reinterpret_cast<const float4*>(&Bs[kk][tx * 8]);
            *reinterpret_cast<float4*>(&b[4]) = *reinterpret_cast<const float4*>(&Bs[kk][tx * 8 + 4]);
            #pragma unroll
            for (int i = 0; i < 8; i++)
                #pragma unroll
                for (int j = 0; j < 8; j++)
                    acc[i][j] += a[i] * b[j];
        }
        __syncthreads();
    }

    // ---- load projection weights for this n-block ----
    for (int idx = tid; idx < BN * 4; idx += 256) {
        int nn = idx >> 2, c = idx & 3;
        int n = block_n + nn;
        Wc[nn][c] = (c < 2) ? W2l[n * 2 + c] : W2r[n * 2 + (c - 2)];
    }
    __syncthreads();

    // ---- epilogue: bias + relu in-register, project to 4 outputs, reduce ----
    #pragma unroll
    for (int i = 0; i < 8; i++) {
        const int m = block_m + ty * 8 + i;
        float s0 = 0.f, s1 = 0.f, s2 = 0.f, s3 = 0.f;
        #pragma unroll
        for (int j = 0; j < 8; j++) {
            const int nn = tx * 8 + j;
            float hv = fmaxf(acc[i][j] + b1[block_n + nn], 0.f);
            s0 += hv * Wc[nn][0];
            s1 += hv * Wc[nn][1];
            s2 += hv * Wc[nn][2];
            s3 += hv * Wc[nn][3];
        }
        // reduce across the 16 threads (tx) sharing this row; they sit in one
        // half-warp (lane = (ty&1)*16 + tx), so xor-shuffles of 1,2,4,8 stay inside.
        #pragma unroll
        for (int off = 8; off > 0; off >>= 1) {
            s0 += __shfl_xor_sync(0xffffffff, s0, off);
            s1 += __shfl_xor_sync(0xffffffff, s1, off);
            s2 += __shfl_xor_sync(0xffffffff, s2, off);
            s3 += __shfl_xor_sync(0xffffffff, s3, off);
        }
        if (tx == 0 && m < N_NODES) {
            atomicAdd(&g_pq[m * 4 + 0], s0);
            atomicAdd(&g_pq[m * 4 + 1], s1);
            atomicAdd(&g_pq[m * 4 + 2], s2);
            atomicAdd(&g_pq[m * 4 + 3], s3);
        }
    }
}

// ---------------- scatter projected messages: q[dst] += pl[src] (2 floats) ---
__global__ void scatter_q_kernel(const int* __restrict__ edge_index) {
    long long e = (long long)blockIdx.x * blockDim.x + threadIdx.x;
    if (e >= N_EDGES) return;
    int src = edge_index[e];
    int dst = edge_index[N_EDGES + e];
    float p0 = g_pq[src * 4 + 0];
    float p1 = g_pq[src * 4 + 1];
    atomicAdd(&g_q[dst * 2 + 0], p0);
    atomicAdd(&g_q[dst * 2 + 1], p1);
}

// ---------------- final: combine + log_softmax --------------------------------
__global__ void final_kernel(const float* __restrict__ b2,
                             float* __restrict__ out) {
    int n = blockIdx.x * blockDim.x + threadIdx.x;
    if (n >= N_NODES) return;
    const float invd = g_deg[n];
    float o0 = g_q[n * 2 + 0] * invd + b2[0] + g_pq[n * 4 + 2];
    float o1 = g_q[n * 2 + 1] * invd + b2[1] + g_pq[n * 4 + 3];
    float m = fmaxf(o0, o1);
    float lse = m + logf(expf(o0 - m) + expf(o1 - m));
    out[n * 2 + 0] = o0 - lse;
    out[n * 2 + 1] = o1 - lse;
}

// ---------------- launcher ----------------------------------------------------
extern "C" void kernel_launch(void* const* d_in, const int* in_sizes, int n_in,
                              void* d_out, int out_size) {
    const float* x    = (const float*)d_in[0];
    const float* W1l  = (const float*)d_in[1];
    const float* b1   = (const float*)d_in[2];
    const float* W1r  = (const float*)d_in[3];
    const float* W2l  = (const float*)d_in[4];
    const float* b2   = (const float*)d_in[5];
    const float* W2r  = (const float*)d_in[6];
    const int*   ei   = (const int*)d_in[7];
    float* out = (float*)d_out;

    zero_kernel<<<1024, 256>>>();

    {
        long long threads = (long long)N_EDGES * 32;
        int blocks = (int)((threads + 255) / 256);
        scatter1_kernel<<<blocks, 256>>>(x, ei);
    }

    finalize_deg_kernel<<<(N_NODES + 255) / 256, 256>>>();

    {
        dim3 grid(HID_DIM / 128, (N_NODES + 127) / 128);
        gemm1_kernel<<<grid, 256>>>(x, W1l, b1, W1r, W2l, W2r);
    }

    scatter_q_kernel<<<(N_EDGES + 255) / 256, 256>>>(ei);

    final_kernel<<<(N_NODES + 255) / 256, 256>>>(b2, out);
}

// round 3
// speedup vs baseline: 4.0107x; 1.5779x over previous
#include <cuda_runtime.h>
#include <math.h>
#include <stdint.h>

#define N_NODES 50000
#define N_EDGES 600000
#define IN_DIM  128
#define HID_DIM 512
#define OUT_DIM 2

// ---------------- scratch ----------------------------------------------------
__device__ float g_agg1[N_NODES * IN_DIM];  // 25.6 MB: sum of x over in-edges
__device__ float g_deg [N_NODES];           // in-degree -> inverted in place
__device__ float g_pq  [N_NODES * 4];       // per node: pl0,pl1 (h@W2l), pr0,pr1 (h@W2r)
__device__ float g_q   [N_NODES * 2];       // scattered pl sums

// ---------------- zero scratch ----------------------------------------------
__global__ void zero_kernel() {
    const long long n_agg = (long long)N_NODES * IN_DIM;
    const long long total = n_agg + N_NODES + N_NODES * 4 + N_NODES * 2;
    for (long long i = (long long)blockIdx.x * blockDim.x + threadIdx.x;
         i < total; i += (long long)gridDim.x * blockDim.x) {
        if (i < n_agg) g_agg1[i] = 0.f;
        else {
            long long r = i - n_agg;
            if (r < N_NODES) g_deg[r] = 0.f;
            else if (r < N_NODES + (long long)N_NODES * 4) g_pq[r - N_NODES] = 0.f;
            else g_q[r - N_NODES - (long long)N_NODES * 4] = 0.f;
        }
    }
}

// ---------------- scatter layer-1: agg1[dst] += x[src] (d=128) --------------
__global__ void scatter1_kernel(const float* __restrict__ x,
                                const int* __restrict__ edge_index) {
    long long tid = (long long)blockIdx.x * blockDim.x + threadIdx.x;
    long long e = tid >> 5;
    int lane = (int)(tid & 31);
    if (e >= N_EDGES) return;
    int src = edge_index[e];
    int dst = edge_index[N_EDGES + e];
    const float4 v = *reinterpret_cast<const float4*>(x + (long long)src * IN_DIM + lane * 4);
    float* base = g_agg1 + (long long)dst * IN_DIM + lane * 4;
    atomicAdd(base + 0, v.x);
    atomicAdd(base + 1, v.y);
    atomicAdd(base + 2, v.z);
    atomicAdd(base + 3, v.w);
    if (lane == 0) atomicAdd(&g_deg[dst], 1.0f);
}

// ---------------- invert degrees --------------------------------------------
__global__ void finalize_deg_kernel() {
    int i = blockIdx.x * blockDim.x + threadIdx.x;
    if (i < N_NODES) g_deg[i] = 1.0f / fmaxf(g_deg[i], 1.0f);
}

// ---------------- helpers -----------------------------------------------------
__device__ __forceinline__ float f2tf32(float f) {
    uint32_t u;
    asm("cvt.rna.tf32.f32 %0, %1;" : "=r"(u) : "f"(f));
    return __uint_as_float(u);
}

__device__ __forceinline__ void mma_tf32(float& d0, float& d1, float& d2, float& d3,
                                         uint32_t a0, uint32_t a1, uint32_t a2, uint32_t a3,
                                         uint32_t b0, uint32_t b1) {
    asm volatile(
        "mma.sync.aligned.m16n8k8.row.col.f32.tf32.tf32.f32 "
        "{%0,%1,%2,%3}, {%4,%5,%6,%7}, {%8,%9}, {%0,%1,%2,%3};"
        : "+f"(d0), "+f"(d1), "+f"(d2), "+f"(d3)
        : "r"(a0), "r"(a1), "r"(a2), "r"(a3), "r"(b0), "r"(b1));
}

// ---------------- layer-1 GEMM on tensor cores, fused layer-2 projection -----
// h_row = relu( (agg1*invd) @ W1l + b1 + x @ W1r )     [never stored]
// g_pq[m] += [ h_tile @ W2l , h_tile @ W2r ]  (atomic across 4 n-blocks)
// virtual A: [M, K=256]  k<128 -> agg1*invd, else x
// virtual B: [K=256, N=512]  k<128 -> W1l, else W1r
// BM=128, BN=128, BK=16; 256 threads; warp grid 2x4, warp tile 64x32 (tf32 mma)
__global__ __launch_bounds__(256, 2)
void gemm1_kernel(const float* __restrict__ x,
                  const float* __restrict__ W1l,
                  const float* __restrict__ b1,
                  const float* __restrict__ W1r,
                  const float* __restrict__ W2l,
                  const float* __restrict__ W2r) {
    constexpr int BM = 128, BN = 128, BK = 16;
    constexpr int SA = BM + 8;   // stride 136: 8 mod 32 banks -> conflict-free frags
    constexpr int SB = BN + 8;
    __shared__ float As[2][BK][SA];
    __shared__ float Bs[2][BK][SB];
    __shared__ float Wc[BN][4];
    __shared__ float bias_s[BN];

    const int block_m = blockIdx.y * BM;
    const int block_n = blockIdx.x * BN;
    const int tid  = threadIdx.x;
    const int warp = tid >> 5;
    const int lane = tid & 31;
    const int wm = warp >> 2;          // 0..1  -> 64-row slab
    const int wn = warp & 3;           // 0..3  -> 32-col slab
    const int g  = lane >> 2;          // 0..7
    const int t  = lane & 3;           // 0..3

    // ---- loader mappings ----
    const int a_row = tid & 127;           // m within tile
    const int a_k   = (tid >> 7) * 8;      // 0 or 8: covers 8 consecutive k
    const int b_row = tid >> 4;            // 0..15: k within tile
    const int b_col = (tid & 15) * 8;      // 0..120

    const int a_m   = block_m + a_row;
    const bool a_ok = (a_m < N_NODES);
    const float invd = a_ok ? g_deg[a_m] : 0.f;

    // ---- epilogue weights/bias ----
    for (int idx = tid; idx < BN * 4; idx += 256) {
        int nn = idx >> 2, c = idx & 3;
        int n = block_n + nn;
        Wc[nn][c] = (c < 2) ? W2l[n * 2 + c] : W2r[n * 2 + (c - 2)];
    }
    for (int idx = tid; idx < BN; idx += 256) bias_s[idx] = b1[block_n + idx];

    // ---- global-load helper (into registers) ----
    float a_reg[8], b_reg[8];
    auto load_tile = [&](int k0) {
        // A: 8 consecutive k for row a_row
        if (a_ok) {
            if (k0 < IN_DIM) {
                const float4 v0 = *reinterpret_cast<const float4*>(
                    g_agg1 + (long long)a_m * IN_DIM + k0 + a_k);
                const float4 v1 = *reinterpret_cast<const float4*>(
                    g_agg1 + (long long)a_m * IN_DIM + k0 + a_k + 4);
                a_reg[0]=v0.x*invd; a_reg[1]=v0.y*invd; a_reg[2]=v0.z*invd; a_reg[3]=v0.w*invd;
                a_reg[4]=v1.x*invd; a_reg[5]=v1.y*invd; a_reg[6]=v1.z*invd; a_reg[7]=v1.w*invd;
            } else {
                const float4 v0 = *reinterpret_cast<const float4*>(
                    x + (long long)a_m * IN_DIM + (k0 - IN_DIM) + a_k);
                const float4 v1 = *reinterpret_cast<const float4*>(
                    x + (long long)a_m * IN_DIM + (k0 - IN_DIM) + a_k + 4);
                a_reg[0]=v0.x; a_reg[1]=v0.y; a_reg[2]=v0.z; a_reg[3]=v0.w;
                a_reg[4]=v1.x; a_reg[5]=v1.y; a_reg[6]=v1.z; a_reg[7]=v1.w;
            }
        } else {
            #pragma unroll
            for (int i = 0; i < 8; i++) a_reg[i] = 0.f;
        }
        // B: row k0+b_row, 8 consecutive n
        {
            int k = k0 + b_row;
            const float* W = (k < IN_DIM) ? W1l : W1r;
            int krel = (k < IN_DIM) ? k : (k - IN_DIM);
            const float4 v0 = *reinterpret_cast<const float4*>(
                W + (long long)krel * HID_DIM + block_n + b_col);
            const float4 v1 = *reinterpret_cast<const float4*>(
                W + (long long)krel * HID_DIM + block_n + b_col + 4);
            b_reg[0]=v0.x; b_reg[1]=v0.y; b_reg[2]=v0.z; b_reg[3]=v0.w;
            b_reg[4]=v1.x; b_reg[5]=v1.y; b_reg[6]=v1.z; b_reg[7]=v1.w;
        }
    };
    auto store_tile = [&](int buf) {
        #pragma unroll
        for (int i = 0; i < 8; i++) As[buf][a_k + i][a_row] = f2tf32(a_reg[i]);
        float4 w0, w1;
        w0.x=f2tf32(b_reg[0]); w0.y=f2tf32(b_reg[1]); w0.z=f2tf32(b_reg[2]); w0.w=f2tf32(b_reg[3]);
        w1.x=f2tf32(b_reg[4]); w1.y=f2tf32(b_reg[5]); w1.z=f2tf32(b_reg[6]); w1.w=f2tf32(b_reg[7]);
        *reinterpret_cast<float4*>(&Bs[buf][b_row][b_col])     = w0;
        *reinterpret_cast<float4*>(&Bs[buf][b_row][b_col + 4]) = w1;
    };

    float acc[4][4][4] = {};   // [mi][ni][reg]

    constexpr int NT = (2 * IN_DIM) / BK;   // 16 tiles
    load_tile(0);
    store_tile(0);
    __syncthreads();

    for (int tI = 0; tI < NT; tI++) {
        const int buf = tI & 1;
        if (tI + 1 < NT) load_tile((tI + 1) * BK);

        // ---- mma over 2 k8 steps ----
        #pragma unroll
        for (int ks = 0; ks < 2; ks++) {
            const int kk = ks * 8;
            uint32_t af[4][4], bf[4][2];
            #pragma unroll
            for (int mi = 0; mi < 4; mi++) {
                const int mb = wm * 64 + mi * 16;
                af[mi][0] = __float_as_uint(As[buf][kk + t    ][mb + g    ]);
                af[mi][1] = __float_as_uint(As[buf][kk + t    ][mb + g + 8]);
                af[mi][2] = __float_as_uint(As[buf][kk + t + 4][mb + g    ]);
                af[mi][3] = __float_as_uint(As[buf][kk + t + 4][mb + g + 8]);
            }
            #pragma unroll
            for (int ni = 0; ni < 4; ni++) {
                const int nb = wn * 32 + ni * 8;
                bf[ni][0] = __float_as_uint(Bs[buf][kk + t    ][nb + g]);
                bf[ni][1] = __float_as_uint(Bs[buf][kk + t + 4][nb + g]);
            }
            #pragma unroll
            for (int mi = 0; mi < 4; mi++)
                #pragma unroll
                for (int ni = 0; ni < 4; ni++)
                    mma_tf32(acc[mi][ni][0], acc[mi][ni][1], acc[mi][ni][2], acc[mi][ni][3],
                             af[mi][0], af[mi][1], af[mi][2], af[mi][3],
                             bf[ni][0], bf[ni][1]);
        }

        if (tI + 1 < NT) store_tile(buf ^ 1);
        __syncthreads();
    }

    // ---- epilogue: bias + relu in-register, project to 4 outputs ----
    // thread lane (g,t): acc[mi][ni][r] = D[wm*64+mi*16 + g + (r>=2?8:0)][wn*32+ni*8 + 2t + (r&1)]
    #pragma unroll
    for (int mi = 0; mi < 4; mi++) {
        #pragma unroll
        for (int half = 0; half < 2; half++) {
            const int m = block_m + wm * 64 + mi * 16 + g + half * 8;
            float s0 = 0.f, s1 = 0.f, s2 = 0.f, s3 = 0.f;
            #pragma unroll
            for (int ni = 0; ni < 4; ni++) {
                #pragma unroll
                for (int r = 0; r < 2; r++) {
                    const int nl = wn * 32 + ni * 8 + 2 * t + r;
                    float hv = fmaxf(acc[mi][ni][half * 2 + r] + bias_s[nl], 0.f);
                    s0 += hv * Wc[nl][0];
                    s1 += hv * Wc[nl][1];
                    s2 += hv * Wc[nl][2];
                    s3 += hv * Wc[nl][3];
                }
            }
            // reduce over the t-quad (lanes g*4 + t)
            #pragma unroll
            for (int off = 1; off <= 2; off <<= 1) {
                s0 += __shfl_xor_sync(0xffffffff, s0, off);
                s1 += __shfl_xor_sync(0xffffffff, s1, off);
                s2 += __shfl_xor_sync(0xffffffff, s2, off);
                s3 += __shfl_xor_sync(0xffffffff, s3, off);
            }
            if (t == 0 && m < N_NODES) {
                atomicAdd(&g_pq[m * 4 + 0], s0);
                atomicAdd(&g_pq[m * 4 + 1], s1);
                atomicAdd(&g_pq[m * 4 + 2], s2);
                atomicAdd(&g_pq[m * 4 + 3], s3);
            }
        }
    }
}

// ---------------- scatter projected messages: q[dst] += pl[src] (2 floats) ---
__global__ void scatter_q_kernel(const int* __restrict__ edge_index) {
    long long e = (long long)blockIdx.x * blockDim.x + threadIdx.x;
    if (e >= N_EDGES) return;
    int src = edge_index[e];
    int dst = edge_index[N_EDGES + e];
    float p0 = g_pq[src * 4 + 0];
    float p1 = g_pq[src * 4 + 1];
    atomicAdd(&g_q[dst * 2 + 0], p0);
    atomicAdd(&g_q[dst * 2 + 1], p1);
}

// ---------------- final: combine + log_softmax --------------------------------
__global__ void final_kernel(const float* __restrict__ b2,
                             float* __restrict__ out) {
    int n = blockIdx.x * blockDim.x + threadIdx.x;
    if (n >= N_NODES) return;
    const float invd = g_deg[n];
    float o0 = g_q[n * 2 + 0] * invd + b2[0] + g_pq[n * 4 + 2];
    float o1 = g_q[n * 2 + 1] * invd + b2[1] + g_pq[n * 4 + 3];
    float m = fmaxf(o0, o1);
    float lse = m + logf(expf(o0 - m) + expf(o1 - m));
    out[n * 2 + 0] = o0 - lse;
    out[n * 2 + 1] = o1 - lse;
}

// ---------------- launcher ----------------------------------------------------
extern "C" void kernel_launch(void* const* d_in, const int* in_sizes, int n_in,
                              void* d_out, int out_size) {
    const float* x    = (const float*)d_in[0];
    const float* W1l  = (const float*)d_in[1];
    const float* b1   = (const float*)d_in[2];
    const float* W1r  = (const float*)d_in[3];
    const float* W2l  = (const float*)d_in[4];
    const float* b2   = (const float*)d_in[5];
    const float* W2r  = (const float*)d_in[6];
    const int*   ei   = (const int*)d_in[7];
    float* out = (float*)d_out;

    zero_kernel<<<1024, 256>>>();

    {
        long long threads = (long long)N_EDGES * 32;
        int blocks = (int)((threads + 255) / 256);
        scatter1_kernel<<<blocks, 256>>>(x, ei);
    }

    finalize_deg_kernel<<<(N_NODES + 255) / 256, 256>>>();

    {
        dim3 grid(HID_DIM / 128, (N_NODES + 127) / 128);
        gemm1_kernel<<<grid, 256>>>(x, W1l, b1, W1r, W2l, W2r);
    }

    scatter_q_kernel<<<(N_EDGES + 255) / 256, 256>>>(ei);

    final_kernel<<<(N_NODES + 255) / 256, 256>>>(b2, out);
}

// round 4
// speedup vs baseline: 5.5089x; 1.3736x over previous
#include <cuda_runtime.h>
#include <cuda_fp16.h>
#include <math.h>
#include <stdint.h>

#define N_NODES 50000
#define N_EDGES 600000
#define IN_DIM  128
#define HID_DIM 512

// ---------------- scratch ----------------------------------------------------
__device__ int   g_cnt[N_NODES];
__device__ int   g_row[N_NODES + 1];
__device__ int   g_cursor[N_NODES];
__device__ int   g_csr[N_EDGES];          // src ids grouped by dst
__device__ float g_invd[N_NODES];
__device__ float g_agg1[N_NODES * IN_DIM]; // mean-aggregated x (pre-scaled)
__device__ float g_pq[N_NODES * 4];        // pl0,pl1 (h@W2l), pr0,pr1 (h@W2r)

// ---------------- 0. zero counters + g_pq -------------------------------------
__global__ void zero_kernel() {
    int i = blockIdx.x * blockDim.x + threadIdx.x;
    if (i < N_NODES) g_cnt[i] = 0;
    if (i < N_NODES * 4) g_pq[i] = 0.f;
}

// ---------------- 1. histogram of dst ------------------------------------------
__global__ void hist_kernel(const int* __restrict__ edge_index) {
    int e = blockIdx.x * blockDim.x + threadIdx.x;
    if (e >= N_EDGES) return;
    atomicAdd(&g_cnt[edge_index[N_EDGES + e]], 1);
}

// ---------------- 2. exclusive scan (single block) -----------------------------
__global__ void scan_kernel() {
    __shared__ int partial[1024];
    const int t = threadIdx.x;
    const int CHUNK = (N_NODES + 1023) / 1024;   // 49
    const int beg = t * CHUNK;
    const int end = min(beg + CHUNK, N_NODES);

    int sum = 0;
    for (int i = beg; i < end; i++) sum += g_cnt[i];
    partial[t] = sum;
    __syncthreads();
    for (int off = 1; off < 1024; off <<= 1) {
        int u = (t >= off) ? partial[t - off] : 0;
        __syncthreads();
        partial[t] += u;
        __syncthreads();
    }
    int run = partial[t] - sum;   // exclusive prefix
    for (int i = beg; i < end; i++) {
        int c = g_cnt[i];
        g_row[i] = run;
        g_cursor[i] = run;
        g_invd[i] = 1.f / fmaxf((float)c, 1.f);
        run += c;
    }
    if (t == 0) g_row[N_NODES] = N_EDGES;
}

// ---------------- 3. reorder edges into CSR ------------------------------------
__global__ void reorder_kernel(const int* __restrict__ edge_index) {
    int e = blockIdx.x * blockDim.x + threadIdx.x;
    if (e >= N_EDGES) return;
    int src = edge_index[e];
    int dst = edge_index[N_EDGES + e];
    int pos = atomicAdd(&g_cursor[dst], 1);
    g_csr[pos] = src;
}

// ---------------- 4. gather-mean aggregation (warp per node, no atomics) -------
__global__ void aggregate1_kernel(const float* __restrict__ x) {
    int warp = (blockIdx.x * blockDim.x + threadIdx.x) >> 5;
    int lane = threadIdx.x & 31;
    if (warp >= N_NODES) return;
    const int beg = g_row[warp];
    const int end = g_row[warp + 1];

    float4 s = make_float4(0.f, 0.f, 0.f, 0.f);
    int e = beg;
    for (; e + 1 < end; e += 2) {
        int s0 = g_csr[e], s1 = g_csr[e + 1];
        float4 v0 = *reinterpret_cast<const float4*>(x + (long long)s0 * IN_DIM + lane * 4);
        float4 v1 = *reinterpret_cast<const float4*>(x + (long long)s1 * IN_DIM + lane * 4);
        s.x += v0.x + v1.x; s.y += v0.y + v1.y;
        s.z += v0.z + v1.z; s.w += v0.w + v1.w;
    }
    if (e < end) {
        int s0 = g_csr[e];
        float4 v0 = *reinterpret_cast<const float4*>(x + (long long)s0 * IN_DIM + lane * 4);
        s.x += v0.x; s.y += v0.y; s.z += v0.z; s.w += v0.w;
    }
    const float invd = g_invd[warp];
    s.x *= invd; s.y *= invd; s.z *= invd; s.w *= invd;
    *reinterpret_cast<float4*>(g_agg1 + (long long)warp * IN_DIM + lane * 4) = s;
}

// ---------------- helpers -----------------------------------------------------
__device__ __forceinline__ void ldsm_x4(uint32_t* r, uint32_t addr) {
    asm volatile("ldmatrix.sync.aligned.m8n8.x4.shared.b16 {%0,%1,%2,%3}, [%4];"
                 : "=r"(r[0]), "=r"(r[1]), "=r"(r[2]), "=r"(r[3]) : "r"(addr));
}
__device__ __forceinline__ void ldsm_x2t(uint32_t* r, uint32_t addr) {
    asm volatile("ldmatrix.sync.aligned.m8n8.x2.trans.shared.b16 {%0,%1}, [%2];"
                 : "=r"(r[0]), "=r"(r[1]) : "r"(addr));
}
__device__ __forceinline__ void mma_f16(float* d, const uint32_t* a, const uint32_t* b) {
    asm volatile(
        "mma.sync.aligned.m16n8k16.row.col.f32.f16.f16.f32 "
        "{%0,%1,%2,%3}, {%4,%5,%6,%7}, {%8,%9}, {%0,%1,%2,%3};"
        : "+f"(d[0]), "+f"(d[1]), "+f"(d[2]), "+f"(d[3])
        : "r"(a[0]), "r"(a[1]), "r"(a[2]), "r"(a[3]), "r"(b[0]), "r"(b[1]));
}
__device__ __forceinline__ uint32_t packh2(float a, float b) {
    __half2 h = __floats2half2_rn(a, b);
    return *reinterpret_cast<uint32_t*>(&h);
}

// ---------------- 5. layer-1 GEMM (fp16 TC) fused with layer-2 projection -----
// h_row = relu( agg1m @ W1l + b1 + x @ W1r )   [never stored]
// g_pq[m] += [ h_tile @ W2l , h_tile @ W2r ]   (atomic across 4 n-blocks)
// virtual A: [M, K=256]  k<128 -> g_agg1 (pre-scaled mean), else x
// virtual B: [K=256, N=512]  k<128 -> W1l, else W1r
// BM=128, BN=128, BK=32; 256 threads; warp grid 2x4, warp tile 64x32
__global__ __launch_bounds__(256, 2)
void gemm1_kernel(const float* __restrict__ x,
                  const float* __restrict__ W1l,
                  const float* __restrict__ b1,
                  const float* __restrict__ W1r,
                  const float* __restrict__ W2l,
                  const float* __restrict__ W2r) {
    constexpr int BM = 128, BN = 128, BK = 32;
    constexpr int SA = BK + 8;   // 40 halfs per A row (m-major)   -> 80B stride
    constexpr int SB = BN + 8;   // 136 halfs per B row (k-major)  -> 272B stride
    __shared__ __align__(16) __half As[2][BM][SA];
    __shared__ __align__(16) __half Bs[2][BK][SB];
    __shared__ float Wc[BN][4];
    __shared__ float bias_s[BN];

    const int block_m = blockIdx.y * BM;
    const int block_n = blockIdx.x * BN;
    const int tid  = threadIdx.x;
    const int warp = tid >> 5;
    const int lane = tid & 31;
    const int wm = warp >> 2;          // 0..1 -> 64-row slab
    const int wn = warp & 3;           // 0..3 -> 32-col slab
    const int g  = lane >> 2;
    const int t  = lane & 3;

    // loader mappings
    const int a_row = tid & 127;            // m within tile
    const int a_k   = (tid >> 7) * 16;      // 0 or 16
    const int b_row = tid >> 4;             // 0..15 (also handles b_row+16)
    const int b_col = (tid & 15) * 8;       // 0..120

    const int a_m   = block_m + a_row;
    const bool a_ok = (a_m < N_NODES);

    // epilogue weights/bias
    for (int idx = tid; idx < BN * 4; idx += 256) {
        int nn = idx >> 2, c = idx & 3;
        int n = block_n + nn;
        Wc[nn][c] = (c < 2) ? W2l[n * 2 + c] : W2r[n * 2 + (c - 2)];
    }
    for (int idx = tid; idx < BN; idx += 256) bias_s[idx] = b1[block_n + idx];

    float a_f[16], b_f[16];
    auto load_tile = [&](int k0) {
        if (a_ok) {
            const float* src = (k0 < IN_DIM)
                ? (g_agg1 + (long long)a_m * IN_DIM + k0 + a_k)
                : (x + (long long)a_m * IN_DIM + (k0 - IN_DIM) + a_k);
            #pragma unroll
            for (int q = 0; q < 4; q++) {
                float4 v = *reinterpret_cast<const float4*>(src + q * 4);
                a_f[q*4+0]=v.x; a_f[q*4+1]=v.y; a_f[q*4+2]=v.z; a_f[q*4+3]=v.w;
            }
        } else {
            #pragma unroll
            for (int i = 0; i < 16; i++) a_f[i] = 0.f;
        }
        #pragma unroll
        for (int h = 0; h < 2; h++) {
            int k = k0 + b_row + h * 16;
            const float* W = (k < IN_DIM) ? W1l : W1r;
            int krel = (k < IN_DIM) ? k : (k - IN_DIM);
            const float4 v0 = *reinterpret_cast<const float4*>(
                W + (long long)krel * HID_DIM + block_n + b_col);
            const float4 v1 = *reinterpret_cast<const float4*>(
                W + (long long)krel * HID_DIM + block_n + b_col + 4);
            b_f[h*8+0]=v0.x; b_f[h*8+1]=v0.y; b_f[h*8+2]=v0.z; b_f[h*8+3]=v0.w;
            b_f[h*8+4]=v1.x; b_f[h*8+5]=v1.y; b_f[h*8+6]=v1.z; b_f[h*8+7]=v1.w;
        }
    };
    auto store_tile = [&](int buf) {
        uint4 ua0, ua1;
        ua0.x=packh2(a_f[0],a_f[1]);   ua0.y=packh2(a_f[2],a_f[3]);
        ua0.z=packh2(a_f[4],a_f[5]);   ua0.w=packh2(a_f[6],a_f[7]);
        ua1.x=packh2(a_f[8],a_f[9]);   ua1.y=packh2(a_f[10],a_f[11]);
        ua1.z=packh2(a_f[12],a_f[13]); ua1.w=packh2(a_f[14],a_f[15]);
        *reinterpret_cast<uint4*>(&As[buf][a_row][a_k])     = ua0;
        *reinterpret_cast<uint4*>(&As[buf][a_row][a_k + 8]) = ua1;
        uint4 ub0, ub1;
        ub0.x=packh2(b_f[0],b_f[1]);   ub0.y=packh2(b_f[2],b_f[3]);
        ub0.z=packh2(b_f[4],b_f[5]);   ub0.w=packh2(b_f[6],b_f[7]);
        ub1.x=packh2(b_f[8],b_f[9]);   ub1.y=packh2(b_f[10],b_f[11]);
        ub1.z=packh2(b_f[12],b_f[13]); ub1.w=packh2(b_f[14],b_f[15]);
        *reinterpret_cast<uint4*>(&Bs[buf][b_row][b_col])      = ub0;
        *reinterpret_cast<uint4*>(&Bs[buf][b_row + 16][b_col]) = ub1;
    };

    // per-lane ldmatrix address bases
    const uint32_t as_base = (uint32_t)__cvta_generic_to_shared(&As[0][0][0]);
    const uint32_t bs_base = (uint32_t)__cvta_generic_to_shared(&Bs[0][0][0]);
    const uint32_t a_lane = ((wm * 64 + (lane & 15)) * SA + (lane >> 4) * 8) * 2;
    const uint32_t b_lane = ((lane & 15) * SB + wn * 32) * 2;
    constexpr uint32_t AS_BUF = BM * SA * 2;
    constexpr uint32_t BS_BUF = BK * SB * 2;

    float acc[4][4][4] = {};

    constexpr int NT = (2 * IN_DIM) / BK;   // 8 tiles
    load_tile(0);
    store_tile(0);
    __syncthreads();

    for (int tI = 0; tI < NT; tI++) {
        const int buf = tI & 1;
        if (tI + 1 < NT) load_tile((tI + 1) * BK);

        #pragma unroll
        for (int ks = 0; ks < 2; ks++) {
            const int kk = ks * 16;
            uint32_t af[4][4], bf[4][2];
            #pragma unroll
            for (int mi = 0; mi < 4; mi++)
                ldsm_x4(af[mi], as_base + buf * AS_BUF + a_lane
                                + (mi * 16 * SA + kk) * 2);
            #pragma unroll
            for (int ni = 0; ni < 4; ni++)
                ldsm_x2t(bf[ni], bs_base + buf * BS_BUF + b_lane
                                 + (kk * SB + ni * 8) * 2);
            #pragma unroll
            for (int mi = 0; mi < 4; mi++)
                #pragma unroll
                for (int ni = 0; ni < 4; ni++)
                    mma_f16(acc[mi][ni], af[mi], bf[ni]);
        }

        if (tI + 1 < NT) store_tile(buf ^ 1);
        __syncthreads();
    }

    // epilogue: bias + relu in-register, project to 4 outputs, reduce over t-quad
    #pragma unroll
    for (int mi = 0; mi < 4; mi++) {
        #pragma unroll
        for (int half = 0; half < 2; half++) {
            const int m = block_m + wm * 64 + mi * 16 + g + half * 8;
            float s0 = 0.f, s1 = 0.f, s2 = 0.f, s3 = 0.f;
            #pragma unroll
            for (int ni = 0; ni < 4; ni++) {
                #pragma unroll
                for (int r = 0; r < 2; r++) {
                    const int nl = wn * 32 + ni * 8 + 2 * t + r;
                    float hv = fmaxf(acc[mi][ni][half * 2 + r] + bias_s[nl], 0.f);
                    s0 += hv * Wc[nl][0];
                    s1 += hv * Wc[nl][1];
                    s2 += hv * Wc[nl][2];
                    s3 += hv * Wc[nl][3];
                }
            }
            #pragma unroll
            for (int off = 1; off <= 2; off <<= 1) {
                s0 += __shfl_xor_sync(0xffffffff, s0, off);
                s1 += __shfl_xor_sync(0xffffffff, s1, off);
                s2 += __shfl_xor_sync(0xffffffff, s2, off);
                s3 += __shfl_xor_sync(0xffffffff, s3, off);
            }
            if (t == 0 && m < N_NODES) {
                atomicAdd(&g_pq[m * 4 + 0], s0);
                atomicAdd(&g_pq[m * 4 + 1], s1);
                atomicAdd(&g_pq[m * 4 + 2], s2);
                atomicAdd(&g_pq[m * 4 + 3], s3);
            }
        }
    }
}

// ---------------- 6. final: gather pl over CSR + combine + log_softmax ---------
__global__ void final_kernel(const float* __restrict__ b2,
                             float* __restrict__ out) {
    int n = blockIdx.x * blockDim.x + threadIdx.x;
    if (n >= N_NODES) return;
    const int beg = g_row[n];
    const int end = g_row[n + 1];
    float s0 = 0.f, s1 = 0.f;
    int e = beg;
    for (; e + 1 < end; e += 2) {
        int u = g_csr[e], v = g_csr[e + 1];
        float2 pu = *reinterpret_cast<const float2*>(&g_pq[u * 4]);
        float2 pv = *reinterpret_cast<const float2*>(&g_pq[v * 4]);
        s0 += pu.x + pv.x; s1 += pu.y + pv.y;
    }
    if (e < end) {
        int u = g_csr[e];
        float2 pu = *reinterpret_cast<const float2*>(&g_pq[u * 4]);
        s0 += pu.x; s1 += pu.y;
    }
    const float invd = g_invd[n];
    float o0 = s0 * invd + b2[0] + g_pq[n * 4 + 2];
    float o1 = s1 * invd + b2[1] + g_pq[n * 4 + 3];
    float m = fmaxf(o0, o1);
    float lse = m + logf(expf(o0 - m) + expf(o1 - m));
    out[n * 2 + 0] = o0 - lse;
    out[n * 2 + 1] = o1 - lse;
}

// ---------------- launcher ----------------------------------------------------
extern "C" void kernel_launch(void* const* d_in, const int* in_sizes, int n_in,
                              void* d_out, int out_size) {
    const float* x    = (const float*)d_in[0];
    const float* W1l  = (const float*)d_in[1];
    const float* b1   = (const float*)d_in[2];
    const float* W1r  = (const float*)d_in[3];
    const float* W2l  = (const float*)d_in[4];
    const float* b2   = (const float*)d_in[5];
    const float* W2r  = (const float*)d_in[6];
    const int*   ei   = (const int*)d_in[7];
    float* out = (float*)d_out;

    zero_kernel<<<(N_NODES * 4 + 255) / 256, 256>>>();
    hist_kernel<<<(N_EDGES + 255) / 256, 256>>>(ei);
    scan_kernel<<<1, 1024>>>();
    reorder_kernel<<<(N_EDGES + 255) / 256, 256>>>(ei);
    {
        int warps_per_block = 8;
        int blocks = (N_NODES + warps_per_block - 1) / warps_per_block;
        aggregate1_kernel<<<blocks, 256>>>(x);
    }
    {
        dim3 grid(HID_DIM / 128, (N_NODES + 127) / 128);
        gemm1_kernel<<<grid, 256>>>(x, W1l, b1, W1r, W2l, W2r);
    }
    final_kernel<<<(N_NODES + 255) / 256, 256>>>(b2, out);
}

// round 6
// speedup vs baseline: 6.8831x; 1.2494x over previous
#include <cuda_runtime.h>
#include <cuda_fp16.h>
#include <math.h>
#include <stdint.h>

#define N_NODES 50000
#define N_PAD   50176
#define N_EDGES 600000
#define IN_DIM  128
#define HID_DIM 512

// ---------------- scratch ----------------------------------------------------
__device__ int   g_cnt[N_NODES];
__device__ int   g_row[N_NODES + 1];
__device__ int   g_cursor[N_NODES];
__device__ int   g_csr[N_EDGES];
__device__ float g_invd[N_NODES];
__device__ __align__(16) __half g_xh  [N_PAD * IN_DIM];   // x as f16 (padded rows zero)
__device__ __align__(16) __half g_aggh[N_PAD * IN_DIM];   // mean-agg as f16 (padded zero)
__device__ __align__(16) __half g_Wh  [256 * HID_DIM];    // [k][n] f16: k<128 W1l else W1r
__device__ float g_pq[N_NODES * 4];

__device__ __forceinline__ uint32_t packh2(float a, float b) {
    __half2 h = __floats2half2_rn(a, b);
    return *reinterpret_cast<uint32_t*>(&h);
}

// ---------------- 0. prep: zero counters/pq + convert x + convert W ------------
__global__ void prep_kernel(const float* __restrict__ x,
                            const float* __restrict__ W1l,
                            const float* __restrict__ W1r) {
    int i = blockIdx.x * blockDim.x + threadIdx.x;
    // zero counters + pq
    if (i < N_NODES) g_cnt[i] = 0;
    if (i < N_NODES * 4) g_pq[i] = 0.f;
    // convert x (one thread per 8 elems)
    const int xtot = N_PAD * IN_DIM / 8;
    if (i < xtot) {
        long long base = (long long)i * 8;
        int m = (int)(base / IN_DIM);
        uint4 o;
        if (m < N_NODES) {
            float4 v0 = *reinterpret_cast<const float4*>(x + base);
            float4 v1 = *reinterpret_cast<const float4*>(x + base + 4);
            o.x = packh2(v0.x, v0.y); o.y = packh2(v0.z, v0.w);
            o.z = packh2(v1.x, v1.y); o.w = packh2(v1.z, v1.w);
        } else o = make_uint4(0, 0, 0, 0);
        *reinterpret_cast<uint4*>(g_xh + base) = o;
    }
    // convert W (one thread per 4 elems)
    const int wtot = 256 * HID_DIM / 4;
    if (i < wtot) {
        int base = i * 4;
        int k = base >> 9;              // /512
        int n = base & 511;
        const float* W = (k < IN_DIM) ? (W1l + k * HID_DIM + n)
                                      : (W1r + (k - IN_DIM) * HID_DIM + n);
        float4 v = *reinterpret_cast<const float4*>(W);
        uint2 o; o.x = packh2(v.x, v.y); o.y = packh2(v.z, v.w);
        *reinterpret_cast<uint2*>(g_Wh + base) = o;
    }
}

// ---------------- 1. histogram --------------------------------------------------
__global__ void hist_kernel(const int* __restrict__ edge_index) {
    int e = blockIdx.x * blockDim.x + threadIdx.x;
    if (e >= N_EDGES) return;
    atomicAdd(&g_cnt[edge_index[N_EDGES + e]], 1);
}

// ---------------- 2. scan -------------------------------------------------------
__global__ void scan_kernel() {
    __shared__ int partial[1024];
    const int t = threadIdx.x;
    const int CHUNK = (N_NODES + 1023) / 1024;
    const int beg = t * CHUNK;
    const int end = min(beg + CHUNK, N_NODES);
    int sum = 0;
    for (int i = beg; i < end; i++) sum += g_cnt[i];
    partial[t] = sum;
    __syncthreads();
    for (int off = 1; off < 1024; off <<= 1) {
        int u = (t >= off) ? partial[t - off] : 0;
        __syncthreads();
        partial[t] += u;
        __syncthreads();
    }
    int run = partial[t] - sum;
    for (int i = beg; i < end; i++) {
        int c = g_cnt[i];
        g_row[i] = run;
        g_cursor[i] = run;
        g_invd[i] = 1.f / fmaxf((float)c, 1.f);
        run += c;
    }
    if (t == 0) g_row[N_NODES] = N_EDGES;
}

// ---------------- 3. reorder ----------------------------------------------------
__global__ void reorder_kernel(const int* __restrict__ edge_index) {
    int e = blockIdx.x * blockDim.x + threadIdx.x;
    if (e >= N_EDGES) return;
    int src = edge_index[e];
    int dst = edge_index[N_EDGES + e];
    int pos = atomicAdd(&g_cursor[dst], 1);
    g_csr[pos] = src;
}

// ---------------- 4. gather-mean aggregation -> f16 ------------------------------
__global__ void aggregate1_kernel(const float* __restrict__ x) {
    int warp = (blockIdx.x * blockDim.x + threadIdx.x) >> 5;
    int lane = threadIdx.x & 31;
    if (warp >= N_PAD) return;
    float4 s = make_float4(0.f, 0.f, 0.f, 0.f);
    if (warp < N_NODES) {
        const int beg = g_row[warp];
        const int end = g_row[warp + 1];
        int e = beg;
        for (; e + 1 < end; e += 2) {
            int s0 = g_csr[e], s1 = g_csr[e + 1];
            float4 v0 = *reinterpret_cast<const float4*>(x + (long long)s0 * IN_DIM + lane * 4);
            float4 v1 = *reinterpret_cast<const float4*>(x + (long long)s1 * IN_DIM + lane * 4);
            s.x += v0.x + v1.x; s.y += v0.y + v1.y;
            s.z += v0.z + v1.z; s.w += v0.w + v1.w;
        }
        if (e < end) {
            int s0 = g_csr[e];
            float4 v0 = *reinterpret_cast<const float4*>(x + (long long)s0 * IN_DIM + lane * 4);
            s.x += v0.x; s.y += v0.y; s.z += v0.z; s.w += v0.w;
        }
        const float invd = g_invd[warp];
        s.x *= invd; s.y *= invd; s.z *= invd; s.w *= invd;
    }
    uint2 o;
    o.x = packh2(s.x, s.y);
    o.y = packh2(s.z, s.w);
    *reinterpret_cast<uint2*>(g_aggh + (long long)warp * IN_DIM + lane * 4) = o;
}

// ---------------- mma helpers ----------------------------------------------------
__device__ __forceinline__ void ldsm_x4(uint32_t* r, uint32_t addr) {
    asm volatile("ldmatrix.sync.aligned.m8n8.x4.shared.b16 {%0,%1,%2,%3}, [%4];"
                 : "=r"(r[0]), "=r"(r[1]), "=r"(r[2]), "=r"(r[3]) : "r"(addr));
}
__device__ __forceinline__ void ldsm_x2t(uint32_t* r, uint32_t addr) {
    asm volatile("ldmatrix.sync.aligned.m8n8.x2.trans.shared.b16 {%0,%1}, [%2];"
                 : "=r"(r[0]), "=r"(r[1]) : "r"(addr));
}
__device__ __forceinline__ void mma_f16(float* d, const uint32_t* a, const uint32_t* b) {
    asm volatile(
        "mma.sync.aligned.m16n8k16.row.col.f32.f16.f16.f32 "
        "{%0,%1,%2,%3}, {%4,%5,%6,%7}, {%8,%9}, {%0,%1,%2,%3};"
        : "+f"(d[0]), "+f"(d[1]), "+f"(d[2]), "+f"(d[3])
        : "r"(a[0]), "r"(a[1]), "r"(a[2]), "r"(a[3]), "r"(b[0]), "r"(b[1]));
}
__device__ __forceinline__ void cp16(uint32_t smem_addr, const void* gptr) {
    asm volatile("cp.async.cg.shared.global [%0], [%1], 16;"
                 :: "r"(smem_addr), "l"(gptr) : "memory");
}

// ---------------- 5. layer-1 GEMM (fp16 HMMA + cp.async), fused projection -------
// BM=128, BN=128, BK=32; 256 threads; warp grid 2x4, warp tile 64x32
__global__ __launch_bounds__(256, 2)
void gemm1_kernel(const float* __restrict__ b1,
                  const float* __restrict__ W2l,
                  const float* __restrict__ W2r) {
    constexpr int BM = 128, BN = 128, BK = 32;
    constexpr int SA = BK + 8;    // 40 halfs = 80B row stride (16B aligned, conflict-free)
    constexpr int SB = BN + 8;    // 136 halfs = 272B row stride
    __shared__ __align__(16) __half As[2][BM][SA];
    __shared__ __align__(16) __half Bs[2][BK][SB];
    __shared__ float Wc[BN][4];
    __shared__ float bias_s[BN];

    const int block_m = blockIdx.y * BM;
    const int block_n = blockIdx.x * BN;
    const int tid  = threadIdx.x;
    const int warp = tid >> 5;
    const int lane = tid & 31;
    const int wm = warp >> 2;
    const int wn = warp & 3;
    const int g  = lane >> 2;
    const int t  = lane & 3;

    // epilogue weights/bias
    for (int idx = tid; idx < BN * 4; idx += 256) {
        int nn = idx >> 2, c = idx & 3;
        int n = block_n + nn;
        Wc[nn][c] = (c < 2) ? W2l[n * 2 + c] : W2r[n * 2 + (c - 2)];
    }
    for (int idx = tid; idx < BN; idx += 256) bias_s[idx] = b1[block_n + idx];

    // cp.async loader mapping (each thread: 2 A chunks + 2 B chunks of 16B)
    const uint32_t as_base = (uint32_t)__cvta_generic_to_shared(&As[0][0][0]);
    const uint32_t bs_base = (uint32_t)__cvta_generic_to_shared(&Bs[0][0][0]);
    constexpr uint32_t AS_BUF = BM * SA * 2;
    constexpr uint32_t BS_BUF = BK * SB * 2;

    auto load_tile = [&](int k0, int buf) {
        // ---- A: 128 rows x 32 halfs = 512 x 16B; thread does ids tid, tid+256 ----
        const __half* asrc = (k0 < IN_DIM) ? g_aggh : g_xh;
        const int krel = (k0 < IN_DIM) ? k0 : (k0 - IN_DIM);
        #pragma unroll
        for (int i = 0; i < 2; i++) {
            int id = tid + i * 256;             // 0..511
            int row = id >> 2;                  // 0..127
            int ch = (id & 3) * 8;              // half offset 0,8,16,24
            cp16(as_base + buf * AS_BUF + (row * SA + ch) * 2,
                 asrc + (long long)(block_m + row) * IN_DIM + krel + ch);
        }
        // ---- B: 32 rows x 128 halfs = 512 x 16B ----
        #pragma unroll
        for (int i = 0; i < 2; i++) {
            int id = tid + i * 256;
            int krow = id >> 4;                 // 0..31
            int ncol = (id & 15) * 8;           // 0..120
            cp16(bs_base + buf * BS_BUF + (krow * SB + ncol) * 2,
                 g_Wh + (k0 + krow) * HID_DIM + block_n + ncol);
        }
        asm volatile("cp.async.commit_group;" ::: "memory");
    };

    const uint32_t a_lane = ((wm * 64 + (lane & 15)) * SA + (lane >> 4) * 8) * 2;
    const uint32_t b_lane = ((lane & 15) * SB + wn * 32) * 2;

    float acc[4][4][4] = {};

    constexpr int NT = (2 * IN_DIM) / BK;   // 8 tiles
    load_tile(0, 0);

    #pragma unroll
    for (int tI = 0; tI < NT; tI++) {
        const int buf = tI & 1;
        if (tI + 1 < NT) {
            load_tile((tI + 1) * BK, buf ^ 1);
            asm volatile("cp.async.wait_group 1;" ::: "memory");
        } else {
            asm volatile("cp.async.wait_group 0;" ::: "memory");
        }
        __syncthreads();

        #pragma unroll
        for (int ks = 0; ks < 2; ks++) {
            const int kk = ks * 16;
            uint32_t af[4][4], bf[4][2];
            #pragma unroll
            for (int mi = 0; mi < 4; mi++)
                ldsm_x4(af[mi], as_base + buf * AS_BUF + a_lane + (mi * 16 * SA + kk) * 2);
            #pragma unroll
            for (int ni = 0; ni < 4; ni++)
                ldsm_x2t(bf[ni], bs_base + buf * BS_BUF + b_lane + (kk * SB + ni * 8) * 2);
            #pragma unroll
            for (int mi = 0; mi < 4; mi++)
                #pragma unroll
                for (int ni = 0; ni < 4; ni++)
                    mma_f16(acc[mi][ni], af[mi], bf[ni]);
        }
        __syncthreads();
    }

    // epilogue: bias + relu in-register, project to 4 outputs, reduce over t-quad
    #pragma unroll
    for (int mi = 0; mi < 4; mi++) {
        #pragma unroll
        for (int half = 0; half < 2; half++) {
            const int m = block_m + wm * 64 + mi * 16 + g + half * 8;
            float s0 = 0.f, s1 = 0.f, s2 = 0.f, s3 = 0.f;
            #pragma unroll
            for (int ni = 0; ni < 4; ni++) {
                #pragma unroll
                for (int r = 0; r < 2; r++) {
                    const int nl = wn * 32 + ni * 8 + 2 * t + r;
                    float hv = fmaxf(acc[mi][ni][half * 2 + r] + bias_s[nl], 0.f);
                    s0 += hv * Wc[nl][0];
                    s1 += hv * Wc[nl][1];
                    s2 += hv * Wc[nl][2];
                    s3 += hv * Wc[nl][3];
                }
            }
            #pragma unroll
            for (int off = 1; off <= 2; off <<= 1) {
                s0 += __shfl_xor_sync(0xffffffff, s0, off);
                s1 += __shfl_xor_sync(0xffffffff, s1, off);
                s2 += __shfl_xor_sync(0xffffffff, s2, off);
                s3 += __shfl_xor_sync(0xffffffff, s3, off);
            }
            if (t == 0 && m < N_NODES) {
                atomicAdd(&g_pq[m * 4 + 0], s0);
                atomicAdd(&g_pq[m * 4 + 1], s1);
                atomicAdd(&g_pq[m * 4 + 2], s2);
                atomicAdd(&g_pq[m * 4 + 3], s3);
            }
        }
    }
}

// ---------------- 6. final: gather pl over CSR + combine + log_softmax -----------
__global__ void final_kernel(const float* __restrict__ b2,
                             float* __restrict__ out) {
    int n = blockIdx.x * blockDim.x + threadIdx.x;
    if (n >= N_NODES) return;
    const int beg = g_row[n];
    const int end = g_row[n + 1];
    float s0 = 0.f, s1 = 0.f;
    int e = beg;
    for (; e + 1 < end; e += 2) {
        int u = g_csr[e], v = g_csr[e + 1];
        float2 pu = *reinterpret_cast<const float2*>(&g_pq[u * 4]);
        float2 pv = *reinterpret_cast<const float2*>(&g_pq[v * 4]);
        s0 += pu.x + pv.x; s1 += pu.y + pv.y;
    }
    if (e < end) {
        int u = g_csr[e];
        float2 pu = *reinterpret_cast<const float2*>(&g_pq[u * 4]);
        s0 += pu.x; s1 += pu.y;
    }
    const float invd = g_invd[n];
    float o0 = s0 * invd + b2[0] + g_pq[n * 4 + 2];
    float o1 = s1 * invd + b2[1] + g_pq[n * 4 + 3];
    float m = fmaxf(o0, o1);
    float lse = m + logf(expf(o0 - m) + expf(o1 - m));
    out[n * 2 + 0] = o0 - lse;
    out[n * 2 + 1] = o1 - lse;
}

// ---------------- launcher ---------------------------------------------------------
extern "C" void kernel_launch(void* const* d_in, const int* in_sizes, int n_in,
                              void* d_out, int out_size) {
    const float* x    = (const float*)d_in[0];
    const float* W1l  = (const float*)d_in[1];
    const float* b1   = (const float*)d_in[2];
    const float* W1r  = (const float*)d_in[3];
    const float* W2l  = (const float*)d_in[4];
    const float* b2   = (const float*)d_in[5];
    const float* W2r  = (const float*)d_in[6];
    const int*   ei   = (const int*)d_in[7];
    float* out = (float*)d_out;

    // prep covers max(N_NODES*4, N_PAD*IN_DIM/8, 256*512/4)
    int prep_threads = N_PAD * IN_DIM / 8;   // 802816 (largest)
    prep_kernel<<<(prep_threads + 255) / 256, 256>>>(x, W1l, W1r);
    hist_kernel<<<(N_EDGES + 255) / 256, 256>>>(ei);
    scan_kernel<<<1, 1024>>>();
    reorder_kernel<<<(N_EDGES + 255) / 256, 256>>>(ei);
    aggregate1_kernel<<<(N_PAD * 32 + 255) / 256, 256>>>(x);

    {
        dim3 grid(HID_DIM / 128, (N_PAD + 127) / 128);
        gemm1_kernel<<<grid, 256>>>(b1, W2l, W2r);
    }

    final_kernel<<<(N_NODES + 255) / 256, 256>>>(b2, out);
}